// round 17
// baseline (speedup 1.0000x reference)
#include <cuda_runtime.h>
#include <cuda_fp16.h>
#include <cstdint>

#define NNODES 50000
#define NEDGES 800000
#define FDIM   128
#define HDIM2  256

// ---------------- scratch ----------------
__device__ __align__(16) __half g_embh[4096 * FDIM];             // emb as fp16
__device__ __align__(16) __half g_ah[(size_t)NNODES * FDIM];     // A_hat*E[x] fp16
__device__ __align__(16) __half g_h1h[(size_t)NNODES * HDIM2];   // h1 fp16
__device__ __align__(16) __half g_th[(size_t)NNODES * FDIM];     // h1 @ W2 fp16
__device__ float g_invs[NNODES];
__device__ int   g_deg[NNODES];        // zero at entry of every run (see scan)
__device__ int   g_ptr[NNODES + 1];
__device__ int   g_cur[NNODES];
__device__ __align__(16) int4 g_adj[NEDGES];  // (xi[src], src, norm, 0) by dst
__device__ int   g_xi[NNODES];
// fp16 transposed weights: W1T [256][128], W2T [128][256]
__device__ __align__(16) __half g_w1t[HDIM2 * FDIM];
__device__ __align__(16) __half g_w2t[FDIM * HDIM2];

// ---------------- helpers ----------------
__device__ __forceinline__ uint32_t smem_u32(const void* p) {
    uint32_t a;
    asm("{ .reg .u64 t; cvta.to.shared.u64 t, %1; cvt.u32.u64 %0, t; }"
        : "=r"(a) : "l"(p));
    return a;
}

#define LDSM4(r, a) asm volatile( \
    "ldmatrix.sync.aligned.m8n8.x4.shared.b16 {%0,%1,%2,%3}, [%4];" \
    : "=r"((r)[0]), "=r"((r)[1]), "=r"((r)[2]), "=r"((r)[3]) : "r"(a))
#define LDSM2(r, a) asm volatile( \
    "ldmatrix.sync.aligned.m8n8.x2.shared.b16 {%0,%1}, [%2];" \
    : "=r"((r)[0]), "=r"((r)[1]) : "r"(a))
#define MMA_F16(c, a, b) asm volatile( \
    "mma.sync.aligned.m16n8k16.row.col.f32.f16.f16.f32 " \
    "{%0,%1,%2,%3}, {%4,%5,%6,%7}, {%8,%9}, {%0,%1,%2,%3};" \
    : "+f"((c)[0]), "+f"((c)[1]), "+f"((c)[2]), "+f"((c)[3]) \
    : "r"((a)[0]), "r"((a)[1]), "r"((a)[2]), "r"((a)[3]), \
      "r"((b)[0]), "r"((b)[1]))
#define CP16(dst, src) asm volatile( \
    "cp.async.cg.shared.global [%0], [%1], 16;" :: "r"(dst), "l"(src))
#define CP_COMMIT() asm volatile("cp.async.commit_group;")
#define CP_WAIT0()  asm volatile("cp.async.wait_group 0;")

// block-local dtype detect: int64 little-endian node ids < 2^31 -> odd 32-bit
// words all zero; int32 -> odd words are random node ids (64 of them ~never all 0)
__device__ __forceinline__ int block_is32(const unsigned int* __restrict__ w) {
    __shared__ int s32;
    if (threadIdx.x == 0) s32 = 0;
    __syncthreads();
    if (threadIdx.x < 64 && w[2 * threadIdx.x + 1]) s32 = 1;
    __syncthreads();
    return s32;
}
__device__ __forceinline__ int ld_edge(const void* ei, int is32, int idx) {
    return is32 ? ((const int*)ei)[idx] : (int)((const long long*)ei)[idx];
}

// ---------------- 1: fused prep: deg count + x convert + emb2h + wt ----------
__global__ void prep_kernel(const void* __restrict__ ei,
                            const void* __restrict__ x,
                            const float* __restrict__ emb,
                            const float* __restrict__ W1,
                            const float* __restrict__ W2) {
    int is32 = block_is32((const unsigned int*)ei);
    int t = blockIdx.x * blockDim.x + threadIdx.x;
    if (t < NEDGES) {
        int d = ld_edge(ei, is32, NEDGES + t);
        atomicAdd(&g_deg[d], 1);
    }
    if (t < NNODES) {
        g_xi[t] = is32 ? ((const int*)x)[t] : (int)((const long long*)x)[t];
    }
    if (t < 4096 * FDIM / 4) {           // emb -> fp16, 4 floats/thread
        float4 v = reinterpret_cast<const float4*>(emb)[t];
        __half2 h0 = __float22half2_rn(make_float2(v.x, v.y));
        __half2 h1 = __float22half2_rn(make_float2(v.z, v.w));
        reinterpret_cast<uint2*>(g_embh)[t] =
            make_uint2(*reinterpret_cast<uint32_t*>(&h0),
                       *reinterpret_cast<uint32_t*>(&h1));
    }
    if (t < FDIM * HDIM2) {              // W1: [128][256] -> W1T [256][128]
        int n = t / FDIM, k = t % FDIM;
        g_w1t[(size_t)n * FDIM + k] = __float2half(W1[(size_t)k * HDIM2 + n]);
    } else if (t < 2 * FDIM * HDIM2) {   // W2: [256][128] -> W2T [128][256]
        int u = t - FDIM * HDIM2;
        int n = u / HDIM2, k = u % HDIM2;
        g_w2t[(size_t)n * HDIM2 + k] = __float2half(W2[(size_t)k * FDIM + n]);
    }
}

// ---------------- 2: scan deg -> ptr/cur, invs; zero deg for next replay -----
__global__ __launch_bounds__(1024)
void scaninvs_kernel() {
    __shared__ int part[1024];
    int t = threadIdx.x;
    int lo = t * 49;
    int hi = lo + 49; if (hi > NNODES) hi = NNODES;
    int sum = 0;
    for (int i = lo; i < hi; i++) sum += g_deg[i];
    part[t] = sum;
    __syncthreads();
    for (int off = 1; off < 1024; off <<= 1) {
        int v = (t >= off) ? part[t - off] : 0;
        __syncthreads();
        part[t] += v;
        __syncthreads();
    }
    int base = (t > 0) ? part[t - 1] : 0;
    for (int i = lo; i < hi; i++) {
        int dg = g_deg[i];
        g_ptr[i] = base;
        g_cur[i] = base;
        g_invs[i] = rsqrtf((float)dg + 1.0f);
        g_deg[i] = 0;                     // restore invariant for next replay
        base += dg;
    }
    if (t == 1023) g_ptr[NNODES] = base;  // = NEDGES
}

// ---------------- 3: fill packed CSR adjacency, 1 edge/thread ----------------
__global__ void fill_kernel(const void* __restrict__ ei) {
    int is32 = block_is32((const unsigned int*)ei);
    int e = blockIdx.x * blockDim.x + threadIdx.x;
    if (e >= NEDGES) return;
    int s = ld_edge(ei, is32, e);
    int d = ld_edge(ei, is32, NEDGES + e);
    float norm = g_invs[s] * g_invs[d];
    int pos = atomicAdd(&g_cur[d], 1);
    g_adj[pos] = make_int4(g_xi[s], s, __float_as_int(norm), 0);
}

// ---------------- gather: one node per 16-lane half-warp ----------------
__device__ __forceinline__ void fma8(float* a, uint4 u, float nk) {
    const __half2* h = reinterpret_cast<const __half2*>(&u);
#pragma unroll
    for (int q = 0; q < 4; q++) {
        float2 f = __half22float2(h[q]);
        a[2 * q]     += nk * f.x;
        a[2 * q + 1] += nk * f.y;
    }
}

__global__ __launch_bounds__(256)
void gather_kernel(const __half* __restrict__ rows,
                   int use_first, int use_xi_self,
                   const float* __restrict__ bias,
                   float* __restrict__ outf,
                   __half* __restrict__ outh) {
    int gh = (blockIdx.x * blockDim.x + threadIdx.x) >> 4;   // half-warp id = node
    int sub = threadIdx.x & 15;
    if (gh >= NNODES) return;

    float a[8];
#pragma unroll
    for (int j = 0; j < 8; j++) a[j] = 0.f;

    float iv = g_invs[gh];
    int p0 = g_ptr[gh];
    int cnt = g_ptr[gh + 1] - p0;
    const int4* ap = g_adj + p0;

    // self-loop
    {
        int self = use_xi_self ? g_xi[gh] : gh;
        uint4 u = *reinterpret_cast<const uint4*>(rows + (size_t)self * FDIM + sub * 8);
        fma8(a, u, iv * iv);
    }

    int k = 0;
    for (; k + 8 <= cnt; k += 8) {
        int4 e[8];
#pragma unroll
        for (int j = 0; j < 8; j++) e[j] = ap[k + j];
        uint4 u[8];
#pragma unroll
        for (int j = 0; j < 8; j++) {
            int r = use_first ? e[j].x : e[j].y;
            u[j] = *reinterpret_cast<const uint4*>(rows + (size_t)r * FDIM + sub * 8);
        }
#pragma unroll
        for (int j = 0; j < 8; j++)
            fma8(a, u[j], __int_as_float(e[j].z));
    }
    for (; k < cnt; k++) {
        int4 e = ap[k];
        int r = use_first ? e.x : e.y;
        uint4 u = *reinterpret_cast<const uint4*>(rows + (size_t)r * FDIM + sub * 8);
        fma8(a, u, __int_as_float(e.z));
    }

    if (outf) {
        float4 b0 = *reinterpret_cast<const float4*>(bias + sub * 8);
        float4 b1 = *reinterpret_cast<const float4*>(bias + sub * 8 + 4);
        float4 o0 = make_float4(a[0] + b0.x, a[1] + b0.y, a[2] + b0.z, a[3] + b0.w);
        float4 o1 = make_float4(a[4] + b1.x, a[5] + b1.y, a[6] + b1.z, a[7] + b1.w);
        float* op = outf + (size_t)gh * FDIM + sub * 8;
        *reinterpret_cast<float4*>(op) = o0;
        *reinterpret_cast<float4*>(op + 4) = o1;
    } else {
        uint32_t w[4];
#pragma unroll
        for (int q = 0; q < 4; q++) {
            __half2 h = __float22half2_rn(make_float2(a[2 * q], a[2 * q + 1]));
            w[q] = *reinterpret_cast<uint32_t*>(&h);
        }
        *reinterpret_cast<uint4*>(outh + (size_t)gh * FDIM + sub * 8) =
            make_uint4(w[0], w[1], w[2], w[3]);
    }
}

// ---------------- fp16 HMMA GEMM with cp.async double buffering ----------------
// BM=128, BN=64, BK=32; 8 warps 4(m) x 2(n); warp tile 32x32 = 2x4 m16n8k16.
#define STR 56        // smem row stride in fp16
#define BUFB 21504    // bytes per buffer: (128+64)*56*2
#define OFS_B 14336   // B offset within buffer: 128*56*2
__global__ __launch_bounds__(256)
void gemm_f16_kernel(const __half* __restrict__ A,
                     const __half* __restrict__ BT,
                     const float* __restrict__ bias,
                     __half* __restrict__ outh,
                     int M, int Ntot, int K, int do_relu) {
    __shared__ __align__(16) __half sm[2 * BUFB / 2];

    int tid = threadIdx.x;
    int lane = tid & 31;
    int wid = tid >> 5;
    int wm = wid & 3, wn = wid >> 2;
    int row0 = blockIdx.y * 128;
    int n0 = blockIdx.x * 64;
    uint32_t smb = smem_u32(sm);

    float acc[2][4][4];
#pragma unroll
    for (int mt = 0; mt < 2; mt++)
#pragma unroll
        for (int nt = 0; nt < 4; nt++)
#pragma unroll
            for (int q = 0; q < 4; q++) acc[mt][nt][q] = 0.f;

    int arow = tid >> 1, ahalf = tid & 1;     // A: 2 threads/row, 16 fp16 each
    int brow = tid >> 2, bseg = tid & 3;      // B: 4 threads/row, 8 fp16 each
    int nch = K >> 5;

    int agr = row0 + arow; if (agr > M - 1) agr = M - 1;   // clamp (rows unstored)
    const __half* abase = A + (size_t)agr * K + ahalf * 16;
    const __half* bbase = BT + (size_t)(n0 + brow) * K + bseg * 8;
    uint32_t adst = smb + (arow * STR + ahalf * 16) * 2;
    uint32_t bdst = smb + OFS_B + (brow * STR + bseg * 8) * 2;

    // prologue: chunk 0 -> buffer 0
    CP16(adst, abase);
    CP16(adst + 16, abase + 8);
    CP16(bdst, bbase);
    CP_COMMIT();

    for (int c = 0; c < nch; c++) {
        CP_WAIT0();
        __syncthreads();
        uint32_t buf = (c & 1) ? BUFB : 0;
        if (c + 1 < nch) {
            uint32_t nbuf = ((c + 1) & 1) ? BUFB : 0;
            const __half* an = abase + (c + 1) * 32;
            const __half* bn = bbase + (c + 1) * 32;
            CP16(adst + nbuf, an);
            CP16(adst + nbuf + 16, an + 8);
            CP16(bdst + nbuf, bn);
            CP_COMMIT();
        }
#pragma unroll
        for (int ks = 0; ks < 2; ks++) {
            uint32_t ah[2][4], bh[4][2];
#pragma unroll
            for (int mt = 0; mt < 2; mt++) {
                uint32_t ad = smb + buf +
                    ((wm * 32 + mt * 16 + (lane & 15)) * STR +
                     ks * 16 + ((lane >> 4) << 3)) * 2;
                LDSM4(ah[mt], ad);
            }
#pragma unroll
            for (int nt = 0; nt < 4; nt++) {
                uint32_t bd = smb + buf + OFS_B +
                    ((wn * 32 + nt * 8 + (lane & 7)) * STR +
                     ks * 16 + ((lane >> 3) & 1) * 8) * 2;
                LDSM2(bh[nt], bd);
            }
#pragma unroll
            for (int mt = 0; mt < 2; mt++)
#pragma unroll
                for (int nt = 0; nt < 4; nt++)
                    MMA_F16(acc[mt][nt], ah[mt], bh[nt]);
        }
        __syncthreads();
    }

    int g = lane >> 2, t4 = lane & 3;
#pragma unroll
    for (int mt = 0; mt < 2; mt++) {
        int r0g = row0 + wm * 32 + mt * 16 + g;
#pragma unroll
        for (int nt = 0; nt < 4; nt++) {
            int col = n0 + wn * 32 + nt * 8 + 2 * t4;
            float* a = acc[mt][nt];
            if (bias) {
                float2 bv = *reinterpret_cast<const float2*>(bias + col);
                a[0] += bv.x; a[1] += bv.y; a[2] += bv.x; a[3] += bv.y;
            }
            if (do_relu) {
                a[0] = fmaxf(a[0], 0.f); a[1] = fmaxf(a[1], 0.f);
                a[2] = fmaxf(a[2], 0.f); a[3] = fmaxf(a[3], 0.f);
            }
            if (r0g < M) {
                __half2 h = __float22half2_rn(make_float2(a[0], a[1]));
                reinterpret_cast<uint32_t*>(outh)[((size_t)r0g * Ntot + col) >> 1] =
                    *reinterpret_cast<uint32_t*>(&h);
            }
            if (r0g + 8 < M) {
                __half2 h = __float22half2_rn(make_float2(a[2], a[3]));
                reinterpret_cast<uint32_t*>(outh)[((size_t)(r0g + 8) * Ntot + col) >> 1] =
                    *reinterpret_cast<uint32_t*>(&h);
            }
        }
    }
}

// ---------------- launch ----------------
extern "C" void kernel_launch(void* const* d_in, const int* in_sizes, int n_in,
                              void* d_out, int out_size) {
    const void*  x   = d_in[0];
    const void*  ei  = d_in[1];
    const float* emb = (const float*)d_in[2];   // 4096x128
    const float* W1  = (const float*)d_in[3];   // 128x256
    const float* b1  = (const float*)d_in[4];   // 256
    const float* W2  = (const float*)d_in[5];   // 256x128
    const float* b2  = (const float*)d_in[6];   // 128
    float* out = (float*)d_out;                 // 50000x128

    __half *embh, *ah, *h1h, *th, *w1t, *w2t;
    cudaGetSymbolAddress((void**)&embh, g_embh);
    cudaGetSymbolAddress((void**)&ah,   g_ah);
    cudaGetSymbolAddress((void**)&h1h,  g_h1h);
    cudaGetSymbolAddress((void**)&th,   g_th);
    cudaGetSymbolAddress((void**)&w1t,  g_w1t);
    cudaGetSymbolAddress((void**)&w2t,  g_w2t);

    // 1) fused prep: deg count + x convert + emb2h + weight transpose
    prep_kernel<<<(NEDGES + 255) / 256, 256>>>(ei, x, emb, W1, W2);
    // 2) scan deg -> ptr/cur/invs (+ zero deg for replay idempotence)
    scaninvs_kernel<<<1, 1024>>>();
    // 3) fill packed CSR adjacency
    fill_kernel<<<(NEDGES + 255) / 256, 256>>>(ei);
    // 4) gather layer 1 (row = adj.x = xi[src]) -> A fp16    <-- ncu slot
    gather_kernel<<<(NNODES * 16 + 255) / 256, 256>>>(embh, 1, 1, nullptr,
                                                      nullptr, ah);
    // 5) GEMM1: h1 = relu(A @ W1 + b1)   [M=50000, N=256, K=128]
    {
        dim3 grid(HDIM2 / 64, (NNODES + 127) / 128);
        gemm_f16_kernel<<<grid, 256>>>(ah, w1t, b1, h1h,
                                       NNODES, HDIM2, FDIM, 1);
    }
    // 6) GEMM2: t = h1 @ W2              [M=50000, N=128, K=256]
    {
        dim3 grid(FDIM / 64, (NNODES + 127) / 128);
        gemm_f16_kernel<<<grid, 256>>>(h1h, w2t, nullptr, th,
                                       NNODES, FDIM, HDIM2, 0);
    }
    // 7) gather layer 2 (row = adj.y = src) -> out fp32 (self-loop + bias fused)
    gather_kernel<<<(NNODES * 16 + 255) / 256, 256>>>(th, 0, 0, b2,
                                                      out, nullptr);
}